// round 12
// baseline (speedup 1.0000x reference)
#include <cuda_runtime.h>
#include <cuda_bf16.h>
#include <math.h>

// ============================================================================
// SpectralDiscrepancyModule — tf32 tensor GEMMs (proven fast path), bf16 A,
// smem-resident Householder QR.
// B=4096, H=1024, HALF=512, NCOMP=8, 3 pairs, 5 power-iteration steps.
// ============================================================================

#define BD   4096
#define HD   1024
#define HF   512
#define NC   8

// ------------------------- device scratch (no runtime alloc allowed) -------
__device__ float          g_P[3][BD * HF];   // normalized projections (24 MB)
__device__ __nv_bfloat16  g_A[3][BD * BD];   // 1 - sigmoid(Pa Pb^T)   (96 MB)
__device__ float          g_d[3][BD];        // deg^{-1/2}
__device__ float          g_V[3][BD * NC];   // current eigvec block (Q)
__device__ float          g_X[3][BD * NC];   // d ⊙ V
__device__ float          g_LV[3][BD * NC];  // L @ V (QR workspace)

// ============================================================================
// 1 - sigmoid(x) = 1/(1+e^x) for |x| <= 1 (rows unit-norm -> |dot|<=1).
// Odd tanh Taylor series; abs err <= 3e-8 on [-1,1]. FMA pipe only.
// ============================================================================
__device__ __forceinline__ float one_minus_sigmoid(float x) {
    float u = x * x;
    float q =                8.76984e-7f;
    q = fmaf(q, u,         -8.65551e-6f);
    q = fmaf(q, u,          8.5427532e-5f);
    q = fmaf(q, u,         -8.4325397e-4f);
    q = fmaf(q, u,          8.3333333e-3f);
    q = fmaf(q, u,         -8.3333333e-2f);
    q = fmaf(q, u,          1.0f);
    return fmaf(x * q, -0.25f, 0.5f);
}

// ============================================================================
// tf32 tensor-core NT-GEMM core (round-9 proven): C[i,j] = sum_k A[i,k]*B[j,k]
// CTA tile 128x128, 256 thr = 8 warps (2m x 4n), warp tile 64x32.
// mma.sync.m16n8k8 tf32; K-chunk 16, double-buffered smem, row stride 20
// floats (conflict-free fragment LDS). cvt.rna.tf32.f32 at smem store.
// mode 0: fp32 out, C += bias[j];   mode 1: bf16 out, C = 1 - sigmoid(C)
// ============================================================================
#define SROW 20                       // smem row stride (floats)

__device__ __forceinline__ void cvst(float* dst, float4 v) {
    uint4 t;
    asm("cvt.rna.tf32.f32 %0, %1;" : "=r"(t.x) : "f"(v.x));
    asm("cvt.rna.tf32.f32 %0, %1;" : "=r"(t.y) : "f"(v.y));
    asm("cvt.rna.tf32.f32 %0, %1;" : "=r"(t.z) : "f"(v.z));
    asm("cvt.rna.tf32.f32 %0, %1;" : "=r"(t.w) : "f"(v.w));
    *(uint4*)dst = t;
}

__device__ __forceinline__ void mma8(float* c, const unsigned* a, const unsigned* b) {
    asm volatile(
        "mma.sync.aligned.m16n8k8.row.col.f32.tf32.tf32.f32 "
        "{%0,%1,%2,%3}, {%4,%5,%6,%7}, {%8,%9}, {%0,%1,%2,%3};"
        : "+f"(c[0]), "+f"(c[1]), "+f"(c[2]), "+f"(c[3])
        : "r"(a[0]), "r"(a[1]), "r"(a[2]), "r"(a[3]), "r"(b[0]), "r"(b[1]));
}

__device__ __forceinline__ void gemm_tf32(const float* __restrict__ Ag,
                                          const float* __restrict__ Bg,
                                          void* __restrict__ Cg,
                                          const float* __restrict__ bias,
                                          int lda, int ldc, int nchunk, int mode) {
    __shared__ float As[2][128 * SROW];
    __shared__ float Bs[2][128 * SROW];

    const int tid  = threadIdx.x;
    const int lane = tid & 31;
    const int wm   = (tid >> 5) >> 2;      // 0..1
    const int wn   = (tid >> 5) & 3;       // 0..3
    const int m0   = blockIdx.y * 128;
    const int n0   = blockIdx.x * 128;

    const int ldrow = tid >> 2;            // 0..63
    const int ldcol = (tid & 3) << 2;      // 0,4,8,12
    const float* Ap0 = Ag + (size_t)(m0 + ldrow) * lda + ldcol;
    const float* Ap1 = Ap0 + (size_t)64 * lda;
    const float* Bp0 = Bg + (size_t)(n0 + ldrow) * lda + ldcol;
    const float* Bp1 = Bp0 + (size_t)64 * lda;
    const int sst = ldrow * SROW + ldcol;

    float acc[4][4][4];
#pragma unroll
    for (int mt = 0; mt < 4; mt++)
#pragma unroll
        for (int nt = 0; nt < 4; nt++)
#pragma unroll
            for (int i = 0; i < 4; i++) acc[mt][nt][i] = 0.f;

    float4 ca0, ca1, cb0, cb1;
#define LDGC(kt) { ca0 = *(const float4*)(Ap0 + (kt) * 16); \
                   ca1 = *(const float4*)(Ap1 + (kt) * 16); \
                   cb0 = *(const float4*)(Bp0 + (kt) * 16); \
                   cb1 = *(const float4*)(Bp1 + (kt) * 16); }
#define STSC(b)  { cvst(&As[b][sst], ca0); cvst(&As[b][sst + 64 * SROW], ca1); \
                   cvst(&Bs[b][sst], cb0); cvst(&Bs[b][sst + 64 * SROW], cb1); }

    LDGC(0); STSC(0);
    LDGC(1);
    __syncthreads();

    const int arow = (lane >> 2);
    const int acol = (lane & 3);

#pragma unroll 2
    for (int kt = 0; kt < nchunk; kt++) {
        const int buf = kt & 1;
        if (kt < nchunk - 1) STSC(buf ^ 1);
        if (kt < nchunk - 2) LDGC(kt + 2);
#pragma unroll
        for (int kk = 0; kk < 16; kk += 8) {
            unsigned afr[4][4], bfr[4][2];
#pragma unroll
            for (int mt = 0; mt < 4; mt++) {
                const float* ab = &As[buf][(wm * 64 + mt * 16 + arow) * SROW + kk + acol];
                afr[mt][0] = __float_as_uint(ab[0]);
                afr[mt][1] = __float_as_uint(ab[8 * SROW]);
                afr[mt][2] = __float_as_uint(ab[4]);
                afr[mt][3] = __float_as_uint(ab[8 * SROW + 4]);
            }
#pragma unroll
            for (int nt = 0; nt < 4; nt++) {
                const float* bb = &Bs[buf][(wn * 32 + nt * 8 + arow) * SROW + kk + acol];
                bfr[nt][0] = __float_as_uint(bb[0]);
                bfr[nt][1] = __float_as_uint(bb[4]);
            }
#pragma unroll
            for (int mt = 0; mt < 4; mt++)
#pragma unroll
                for (int nt = 0; nt < 4; nt++)
                    mma8(acc[mt][nt], afr[mt], bfr[nt]);
        }
        __syncthreads();
    }

#pragma unroll
    for (int mt = 0; mt < 4; mt++) {
        const int r0 = m0 + wm * 64 + mt * 16 + arow;
#pragma unroll
        for (int nt = 0; nt < 4; nt++) {
            const int c0 = n0 + wn * 32 + nt * 8 + acol * 2;
            if (mode == 0) {
                float b0 = bias[c0], b1 = bias[c0 + 1];
                float2 v0, v1;
                v0.x = acc[mt][nt][0] + b0; v0.y = acc[mt][nt][1] + b1;
                v1.x = acc[mt][nt][2] + b0; v1.y = acc[mt][nt][3] + b1;
                *(float2*)((float*)Cg + (size_t)r0 * ldc + c0)       = v0;
                *(float2*)((float*)Cg + (size_t)(r0 + 8) * ldc + c0) = v1;
            } else {
                __nv_bfloat162 v0, v1;
                v0.x = __float2bfloat16_rn(one_minus_sigmoid(acc[mt][nt][0]));
                v0.y = __float2bfloat16_rn(one_minus_sigmoid(acc[mt][nt][1]));
                v1.x = __float2bfloat16_rn(one_minus_sigmoid(acc[mt][nt][2]));
                v1.y = __float2bfloat16_rn(one_minus_sigmoid(acc[mt][nt][3]));
                *(__nv_bfloat162*)((__nv_bfloat16*)Cg + (size_t)r0 * ldc + c0)       = v0;
                *(__nv_bfloat162*)((__nv_bfloat16*)Cg + (size_t)(r0 + 8) * ldc + c0) = v1;
            }
        }
    }
#undef LDGC
#undef STSC
}

__global__ __launch_bounds__(256) void k_proj_tf32(const float* __restrict__ z0,
                                                   const float* __restrict__ z1,
                                                   const float* __restrict__ z2,
                                                   const float* __restrict__ W,
                                                   const float* __restrict__ b) {
    const float* zs = (blockIdx.z == 0) ? z0 : ((blockIdx.z == 1) ? z1 : z2);
    gemm_tf32(zs, W, g_P[blockIdx.z], b, HD, HF, HD / 16, 0);
}

__global__ __launch_bounds__(256) void k_pair_tf32() {
    const int p = blockIdx.z;
    const int pa = (p == 2) ? 1 : 0;       // pairs: (0,1) (0,2) (1,2)
    const int pb = (p == 0) ? 1 : 2;
    gemm_tf32(g_P[pa], g_P[pb], g_A[p], nullptr, HF, BD, HF / 16, 1);
}

// ============================================================================
// Row L2 normalize of projections: p /= max(||p||, 1e-12)
// ============================================================================
__global__ __launch_bounds__(128) void k_norm() {
    __shared__ float sred[4];
    const int p = blockIdx.y, r = blockIdx.x, tid = threadIdx.x;
    float4* Pr = (float4*)(g_P[p] + (size_t)r * HF);
    float4 v = Pr[tid];
    float s = v.x * v.x + v.y * v.y + v.z * v.z + v.w * v.w;
#pragma unroll
    for (int t = 16; t; t >>= 1) s += __shfl_xor_sync(0xffffffffu, s, t);
    if ((tid & 31) == 0) sred[tid >> 5] = s;
    __syncthreads();
    float tot = sred[0] + sred[1] + sred[2] + sred[3];
    float scl = 1.0f / fmaxf(sqrtf(tot), 1e-12f);
    v.x *= scl; v.y *= scl; v.z *= scl; v.w *= scl;
    Pr[tid] = v;
}

// ============================================================================
// d[i] = (max(sum_j A[i,j], 1e-8))^{-1/2}     A is bf16 (8 elems per uint4)
// ============================================================================
__global__ __launch_bounds__(256) void k_degree() {
    __shared__ float sred[8];
    const int p = blockIdx.y, r = blockIdx.x, tid = threadIdx.x;
    const uint4* Ar = (const uint4*)(g_A[p] + (size_t)r * BD);
    float s = 0.f;
#pragma unroll
    for (int q = 0; q < 2; q++) {
        uint4 v = Ar[tid + q * 256];
        float2 f0 = __bfloat1622float2(*(__nv_bfloat162*)&v.x);
        float2 f1 = __bfloat1622float2(*(__nv_bfloat162*)&v.y);
        float2 f2 = __bfloat1622float2(*(__nv_bfloat162*)&v.z);
        float2 f3 = __bfloat1622float2(*(__nv_bfloat162*)&v.w);
        s += ((f0.x + f0.y) + (f1.x + f1.y)) + ((f2.x + f2.y) + (f3.x + f3.y));
    }
#pragma unroll
    for (int t = 16; t; t >>= 1) s += __shfl_xor_sync(0xffffffffu, s, t);
    if ((tid & 31) == 0) sred[tid >> 5] = s;
    __syncthreads();
    if (tid == 0) {
        float tot = 0.f;
        for (int w = 0; w < 8; w++) tot += sred[w];
        g_d[p][r] = 1.0f / sqrtf(fmaxf(tot, 1e-8f));
    }
}

// ============================================================================
// JAX threefry2x32 PRNG — partitionable scheme (modern JAX default):
// per-element 64-bit linear-index counter (0, e); 32-bit output = o0 ^ o1.
// ============================================================================
#define TF_R(r) { x0 += x1; x1 = (x1 << (r)) | (x1 >> (32 - (r))); x1 ^= x0; }
__device__ __forceinline__ void tf_hash(unsigned k0, unsigned k1,
                                        unsigned c0, unsigned c1,
                                        unsigned& o0, unsigned& o1) {
    unsigned ks2 = k0 ^ k1 ^ 0x1BD11BDAu;
    unsigned x0 = c0 + k0, x1 = c1 + k1;
    TF_R(13) TF_R(15) TF_R(26) TF_R(6)   x0 += k1;  x1 += ks2 + 1u;
    TF_R(17) TF_R(29) TF_R(16) TF_R(24)  x0 += ks2; x1 += k0  + 2u;
    TF_R(13) TF_R(15) TF_R(26) TF_R(6)   x0 += k0;  x1 += k1  + 3u;
    TF_R(17) TF_R(29) TF_R(16) TF_R(24)  x0 += k1;  x1 += ks2 + 4u;
    TF_R(13) TF_R(15) TF_R(26) TF_R(6)   x0 += ks2; x1 += k0  + 5u;
    o0 = x0; o1 = x1;
}

__device__ __forceinline__ float bits_to_normal(unsigned bits) {
    float f = __uint_as_float((bits >> 9) | 0x3f800000u) - 1.0f;
    const float lo = -0.99999994f;        // nextafter(-1, 0) in fp32
    float u = f * 2.0f + lo;
    u = fmaxf(lo, u);
    return 1.41421356f * erfinvf(u);
}

__global__ __launch_bounds__(256) void k_init() {
    int gid = blockIdx.x * 256 + threadIdx.x;
    if (gid >= 3 * 32768) return;
    int p = gid >> 15;
    int e = gid & 32767;
    unsigned kp0, kp1, o0, o1;
    tf_hash(0u, 42u, 0u, (unsigned)p, kp0, kp1);   // fold_in(key(42), p)
    tf_hash(kp0, kp1, 0u, (unsigned)e, o0, o1);    // counter = (0, e)
    g_V[p][e] = bits_to_normal(o0 ^ o1);
}

// ============================================================================
// Householder QR of 4096x8 panel, SMEM-RESIDENT (column-major, 128 KB dynamic
// smem). LAPACK sgeqr2 + sorg2r conventions; one CTA per pair.
// which==0: factor g_V;  which==1: factor g_LV.
// ============================================================================
#define SH(k, i) sh[(k) * BD + (i)]

__global__ __launch_bounds__(1024) void k_qr(int which) {
    extern __shared__ float sh[];          // [NC][BD] column-major panel
    const int p = blockIdx.x;
    float* __restrict__ Aw = which ? g_LV[p] : g_V[p];
    const int m = BD;
    const int tid = threadIdx.x;
    const int lane = tid & 31;
    const int wid  = tid >> 5;
    __shared__ float tau[NC];
    __shared__ float red[32][NC];
    __shared__ float sred[32];
    __shared__ float sc[2];                // [0]=1/(alpha-beta), [1]=beta

    for (int i = tid; i < m * NC; i += 1024)
        SH(i & 7, i >> 3) = Aw[i];
    __syncthreads();

    // ---------------- factorization (geqr2) ----------------
    for (int j = 0; j < NC; j++) {
        float s = 0.f;
        for (int i = j + 1 + tid; i < m; i += 1024) {
            float v = SH(j, i);
            s += v * v;
        }
#pragma unroll
        for (int t = 16; t; t >>= 1) s += __shfl_xor_sync(0xffffffffu, s, t);
        __syncthreads();
        if (lane == 0) sred[wid] = s;
        __syncthreads();
        if (tid == 0) {
            float ss = 0.f;
            for (int w = 0; w < 32; w++) ss += sred[w];
            float alpha = SH(j, j);
            float t_, scal, beta;
            if (ss == 0.f) { beta = alpha; t_ = 0.f; scal = 0.f; }
            else {
                float nrm = sqrtf(alpha * alpha + ss);
                beta = (alpha >= 0.f) ? -nrm : nrm;   // LAPACK sign convention
                t_   = (beta - alpha) / beta;
                scal = 1.0f / (alpha - beta);
            }
            tau[j] = t_;
            sc[0] = scal; sc[1] = beta;
        }
        __syncthreads();
        const float scal = sc[0];
        const float tj   = tau[j];
        float w[NC];
#pragma unroll
        for (int k = 0; k < NC; k++) w[k] = 0.f;
        for (int i = j + tid; i < m; i += 1024) {
            float v;
            if (i == j) v = 1.f;
            else { v = SH(j, i) * scal; SH(j, i) = v; }
#pragma unroll
            for (int k = 0; k < NC; k++)
                if (k > j) w[k] += v * SH(k, i);
        }
#pragma unroll
        for (int k = 0; k < NC; k++)
#pragma unroll
            for (int t = 16; t; t >>= 1) w[k] += __shfl_xor_sync(0xffffffffu, w[k], t);
        if (lane == 0) {
#pragma unroll
            for (int k = 0; k < NC; k++) red[wid][k] = w[k];
        }
        __syncthreads();
#pragma unroll
        for (int k = 0; k < NC; k++) {
            float t2 = 0.f;
            for (int ww = 0; ww < 32; ww++) t2 += red[ww][k];
            w[k] = t2;
        }
        for (int i = j + tid; i < m; i += 1024) {
            float v = (i == j) ? 1.f : SH(j, i);
#pragma unroll
            for (int k = 0; k < NC; k++)
                if (k > j) SH(k, i) -= tj * w[k] * v;
        }
        if (tid == 0) SH(j, j) = sc[1];
        __syncthreads();
    }

    // ---------------- form Q (sorg2r) ----------------
    for (int j = NC - 1; j >= 0; j--) {
        const float tj = tau[j];
        if (j < NC - 1) {
            float w[NC];
#pragma unroll
            for (int k = 0; k < NC; k++) w[k] = 0.f;
            for (int i = j + tid; i < m; i += 1024) {
                float v = (i == j) ? 1.f : SH(j, i);
#pragma unroll
                for (int k = 0; k < NC; k++)
                    if (k > j) w[k] += v * SH(k, i);
            }
#pragma unroll
            for (int k = 0; k < NC; k++)
#pragma unroll
                for (int t = 16; t; t >>= 1) w[k] += __shfl_xor_sync(0xffffffffu, w[k], t);
            if (lane == 0) {
#pragma unroll
                for (int k = 0; k < NC; k++) red[wid][k] = w[k];
            }
            __syncthreads();
#pragma unroll
            for (int k = 0; k < NC; k++) {
                float t2 = 0.f;
                for (int ww = 0; ww < 32; ww++) t2 += red[ww][k];
                w[k] = t2;
            }
            for (int i = j + tid; i < m; i += 1024) {
                float v = (i == j) ? 1.f : SH(j, i);
#pragma unroll
                for (int k = 0; k < NC; k++)
                    if (k > j) SH(k, i) -= tj * w[k] * v;
            }
            __syncthreads();
        }
        for (int i = tid; i < m; i += 1024) {
            float val;
            if (i < j)       val = 0.f;
            else if (i == j) val = 1.f - tj;
            else             val = -tj * SH(j, i);
            SH(j, i) = val;
        }
        __syncthreads();
    }

    const float* __restrict__ dv = g_d[p];
    for (int i = tid; i < m * NC; i += 1024) {
        float q = SH(i & 7, i >> 3);
        g_V[p][i] = q;
        g_X[p][i] = dv[i >> 3] * q;
    }
}

// ============================================================================
// LV[i,:] = V[i,:] - d[i] * (A[i,:] @ X)    A bf16; X = d ⊙ V staged in smem
// ============================================================================
__global__ __launch_bounds__(256) void k_matvec() {
    const int p = blockIdx.y;
    const int warp = threadIdx.x >> 5, lane = threadIdx.x & 31;
    const int row = blockIdx.x * 8 + warp;
    __shared__ float sX[512 * NC];
    const __nv_bfloat16* __restrict__ Ar = g_A[p] + (size_t)row * BD;
    const float* __restrict__ Xg = g_X[p];
    float acc[8] = {0, 0, 0, 0, 0, 0, 0, 0};
    for (int t0 = 0; t0 < BD; t0 += 512) {
        __syncthreads();
        for (int i = threadIdx.x; i < 512 * NC / 4; i += 256)
            ((float4*)sX)[i] = ((const float4*)(Xg + t0 * NC))[i];
        __syncthreads();
        for (int t = lane; t < 256; t += 32) {
            __nv_bfloat162 a2 = *(const __nv_bfloat162*)(Ar + t0 + 2 * t);
            float2 af = __bfloat1622float2(a2);
            const float* x0 = sX + (2 * t) * NC;
            const float* x1 = x0 + NC;
#pragma unroll
            for (int k = 0; k < 8; k++)
                acc[k] += af.x * x0[k] + af.y * x1[k];
        }
    }
#pragma unroll
    for (int k = 0; k < 8; k++)
#pragma unroll
        for (int t = 16; t; t >>= 1) acc[k] += __shfl_xor_sync(0xffffffffu, acc[k], t);
    if (lane == 0) {
        float di = g_d[p][row];
#pragma unroll
        for (int k = 0; k < 8; k++)
            g_LV[p][row * NC + k] = g_V[p][row * NC + k] - di * acc[k];
    }
}

// ============================================================================
// out = LayerNorm(GELU(spec @ W_out^T + b_out)) ; spec = concat(V0,V1,V2)
// ============================================================================
__global__ __launch_bounds__(128) void k_final(const float* __restrict__ Wo,
                                               const float* __restrict__ bo,
                                               const float* __restrict__ lg,
                                               const float* __restrict__ lb,
                                               float* __restrict__ out) {
    const int r = blockIdx.x, tid = threadIdx.x;
    __shared__ float spec[24];
    __shared__ float sred[4];
    if (tid < 24) spec[tid] = g_V[tid >> 3][r * NC + (tid & 7)];
    __syncthreads();
    float x[4];
    float s = 0.f;
#pragma unroll
    for (int q = 0; q < 4; q++) {
        int j = tid + q * 128;
        const float* wr = Wo + j * 24;
        float acc = bo[j];
#pragma unroll
        for (int c = 0; c < 24; c++) acc += spec[c] * wr[c];
        float gl = 0.5f * acc * (1.0f + erff(acc * 0.70710678118654752f));
        x[q] = gl; s += gl;
    }
#pragma unroll
    for (int t = 16; t; t >>= 1) s += __shfl_xor_sync(0xffffffffu, s, t);
    if ((tid & 31) == 0) sred[tid >> 5] = s;
    __syncthreads();
    float mu = (sred[0] + sred[1] + sred[2] + sred[3]) * (1.0f / HF);
    float s2 = 0.f;
#pragma unroll
    for (int q = 0; q < 4; q++) {
        float d = x[q] - mu;
        s2 += d * d;
    }
#pragma unroll
    for (int t = 16; t; t >>= 1) s2 += __shfl_xor_sync(0xffffffffu, s2, t);
    __syncthreads();
    if ((tid & 31) == 0) sred[tid >> 5] = s2;
    __syncthreads();
    float var = (sred[0] + sred[1] + sred[2] + sred[3]) * (1.0f / HF);
    float inv = 1.0f / sqrtf(var + 1e-5f);
#pragma unroll
    for (int q = 0; q < 4; q++) {
        int j = tid + q * 128;
        out[(size_t)r * HF + j] = (x[q] - mu) * inv * lg[j] + lb[j];
    }
}

// ============================================================================
// Launch sequence (graph-capturable)
// ============================================================================
extern "C" void kernel_launch(void* const* d_in, const int* in_sizes, int n_in,
                              void* d_out, int out_size) {
    const float* zt = (const float*)d_in[0];
    const float* za = (const float*)d_in[1];
    const float* zf = (const float*)d_in[2];
    const float* Wp = (const float*)d_in[3];
    const float* bp = (const float*)d_in[4];
    const float* Wo = (const float*)d_in[5];
    const float* bo = (const float*)d_in[6];
    const float* lg = (const float*)d_in[7];
    const float* lb = (const float*)d_in[8];
    float* out = (float*)d_out;

    const int QR_SMEM = BD * NC * sizeof(float);   // 128 KB dynamic smem
    cudaFuncSetAttribute(k_qr, cudaFuncAttributeMaxDynamicSharedMemorySize, QR_SMEM);

    k_proj_tf32<<<dim3(HF / 128, BD / 128, 3), 256>>>(zt, za, zf, Wp, bp);
    k_norm<<<dim3(BD, 3), 128>>>();
    k_pair_tf32<<<dim3(BD / 128, BD / 128, 3), 256>>>();
    k_degree<<<dim3(BD, 3), 256>>>();
    k_init<<<(3 * 32768 + 255) / 256, 256>>>();
    k_qr<<<3, 1024, QR_SMEM>>>(0);
    for (int it = 0; it < 5; it++) {
        k_matvec<<<dim3(BD / 8, 3), 256>>>();
        k_qr<<<3, 1024, QR_SMEM>>>(1);
    }
    k_final<<<BD, 128>>>(Wo, bo, lg, lb, out);
}

// round 13
// speedup vs baseline: 1.3225x; 1.3225x over previous
#include <cuda_runtime.h>
#include <cuda_fp16.h>
#include <math.h>

// ============================================================================
// SpectralDiscrepancyModule — fp16 tensor GEMMs, fp32 A-matrix (proven-fast
// consumer set), smem-resident Householder QR.
// B=4096, H=1024, HALF=512, NCOMP=8, 3 pairs, 5 power-iteration steps.
// ============================================================================

#define BD   4096
#define HD   1024
#define HF   512
#define NC   8

// ------------------------- device scratch (no runtime alloc allowed) -------
__device__ float g_P[3][BD * HF];        // normalized projections   (24 MB)
__device__ float g_A[3][BD * BD];        // 1 - sigmoid(Pa Pb^T)     (192 MB)
__device__ float g_d[3][BD];             // deg^{-1/2}
__device__ float g_V[3][BD * NC];        // current eigvec block (Q)
__device__ float g_X[3][BD * NC];        // d ⊙ V
__device__ float g_LV[3][BD * NC];       // L @ V (QR workspace)

// ============================================================================
// 1 - sigmoid(x) = 1/(1+e^x) for |x| <= 1 (rows unit-norm -> |dot|<=1).
// Odd tanh Taylor series; abs err <= 3e-8 on [-1,1]. FMA pipe only.
// ============================================================================
__device__ __forceinline__ float one_minus_sigmoid(float x) {
    float u = x * x;
    float q =                8.76984e-7f;
    q = fmaf(q, u,         -8.65551e-6f);
    q = fmaf(q, u,          8.5427532e-5f);
    q = fmaf(q, u,         -8.4325397e-4f);
    q = fmaf(q, u,          8.3333333e-3f);
    q = fmaf(q, u,         -8.3333333e-2f);
    q = fmaf(q, u,          1.0f);
    return fmaf(x * q, -0.25f, 0.5f);
}

// ============================================================================
// fp16 tensor-core NT-GEMM: C[i,j] = sum_k A[i,k]*B[j,k]  (fp32 accumulate)
// CTA tile 128x128, 256 thr = 8 warps (2m x 4n), warp tile 64x32.
// mma.sync.m16n8k16 f16 (same 10-bit mantissa as tf32, 2x FLOP/inst —
// measured 174us faster than tf32 m16n8k8 across the two GEMMs in R10/R11).
// K-chunk 16, double-buffered half smem, row stride 24 halfs (conflict-free).
// mode 0: C += bias[j];   mode 1: C = 1 - sigmoid(C)     (both fp32 out)
// ============================================================================
#define SROWH 24                      // smem row stride (halfs)

__device__ __forceinline__ uint2 f4h(float4 v) {
    __half2 lo = __floats2half2_rn(v.x, v.y);
    __half2 hi = __floats2half2_rn(v.z, v.w);
    uint2 r;
    r.x = *reinterpret_cast<unsigned*>(&lo);
    r.y = *reinterpret_cast<unsigned*>(&hi);
    return r;
}

__device__ __forceinline__ void mma16(float* c, const unsigned* a, const unsigned* b) {
    asm volatile(
        "mma.sync.aligned.m16n8k16.row.col.f32.f16.f16.f32 "
        "{%0,%1,%2,%3}, {%4,%5,%6,%7}, {%8,%9}, {%0,%1,%2,%3};"
        : "+f"(c[0]), "+f"(c[1]), "+f"(c[2]), "+f"(c[3])
        : "r"(a[0]), "r"(a[1]), "r"(a[2]), "r"(a[3]), "r"(b[0]), "r"(b[1]));
}

__device__ __forceinline__ void gemm_fp16(const float* __restrict__ Ag,
                                          const float* __restrict__ Bg,
                                          float* __restrict__ Cg,
                                          const float* __restrict__ bias,
                                          int lda, int ldc, int nchunk, int mode) {
    __shared__ __half As[2][128 * SROWH];
    __shared__ __half Bs[2][128 * SROWH];

    const int tid  = threadIdx.x;
    const int lane = tid & 31;
    const int wm   = (tid >> 5) >> 2;      // 0..1
    const int wn   = (tid >> 5) & 3;       // 0..3
    const int m0   = blockIdx.y * 128;
    const int n0   = blockIdx.x * 128;

    const int ldrow = tid >> 2;            // 0..63
    const int ldcol = (tid & 3) << 2;      // 0,4,8,12
    const float* Ap0 = Ag + (size_t)(m0 + ldrow) * lda + ldcol;
    const float* Ap1 = Ap0 + (size_t)64 * lda;
    const float* Bp0 = Bg + (size_t)(n0 + ldrow) * lda + ldcol;
    const float* Bp1 = Bp0 + (size_t)64 * lda;
    const int sst = ldrow * SROWH + ldcol;

    float acc[4][4][4];
#pragma unroll
    for (int mt = 0; mt < 4; mt++)
#pragma unroll
        for (int nt = 0; nt < 4; nt++)
#pragma unroll
            for (int i = 0; i < 4; i++) acc[mt][nt][i] = 0.f;

    float4 ca0, ca1, cb0, cb1;
#define LDGC(kt) { ca0 = *(const float4*)(Ap0 + (kt) * 16); \
                   ca1 = *(const float4*)(Ap1 + (kt) * 16); \
                   cb0 = *(const float4*)(Bp0 + (kt) * 16); \
                   cb1 = *(const float4*)(Bp1 + (kt) * 16); }
#define STSC(b)  { *(uint2*)&As[b][sst]               = f4h(ca0); \
                   *(uint2*)&As[b][sst + 64 * SROWH]  = f4h(ca1); \
                   *(uint2*)&Bs[b][sst]               = f4h(cb0); \
                   *(uint2*)&Bs[b][sst + 64 * SROWH]  = f4h(cb1); }

    LDGC(0); STSC(0);
    LDGC(1);
    __syncthreads();

    const int arow = (lane >> 2);          // 0..7
    const int acol = (lane & 3);           // 0..3

#pragma unroll 2
    for (int kt = 0; kt < nchunk; kt++) {
        const int buf = kt & 1;
        if (kt < nchunk - 1) STSC(buf ^ 1);
        if (kt < nchunk - 2) LDGC(kt + 2);
        {
            unsigned afr[4][4], bfr[4][2];
#pragma unroll
            for (int mt = 0; mt < 4; mt++) {
                const __half* ab = &As[buf][(wm * 64 + mt * 16 + arow) * SROWH + 2 * acol];
                afr[mt][0] = *(const unsigned*)(ab);
                afr[mt][1] = *(const unsigned*)(ab + 8 * SROWH);
                afr[mt][2] = *(const unsigned*)(ab + 8);
                afr[mt][3] = *(const unsigned*)(ab + 8 * SROWH + 8);
            }
#pragma unroll
            for (int nt = 0; nt < 4; nt++) {
                const __half* bb = &Bs[buf][(wn * 32 + nt * 8 + arow) * SROWH + 2 * acol];
                bfr[nt][0] = *(const unsigned*)(bb);
                bfr[nt][1] = *(const unsigned*)(bb + 8);
            }
#pragma unroll
            for (int mt = 0; mt < 4; mt++)
#pragma unroll
                for (int nt = 0; nt < 4; nt++)
                    mma16(acc[mt][nt], afr[mt], bfr[nt]);
        }
        __syncthreads();
    }

    // epilogue: fp32 float2 stores (full-sector writes, R9-proven)
#pragma unroll
    for (int mt = 0; mt < 4; mt++) {
        const int r0 = m0 + wm * 64 + mt * 16 + arow;
#pragma unroll
        for (int nt = 0; nt < 4; nt++) {
            const int c0 = n0 + wn * 32 + nt * 8 + acol * 2;
            float2 v0, v1;
            if (mode == 0) {
                float b0 = bias[c0], b1 = bias[c0 + 1];
                v0.x = acc[mt][nt][0] + b0; v0.y = acc[mt][nt][1] + b1;
                v1.x = acc[mt][nt][2] + b0; v1.y = acc[mt][nt][3] + b1;
            } else {
                v0.x = one_minus_sigmoid(acc[mt][nt][0]);
                v0.y = one_minus_sigmoid(acc[mt][nt][1]);
                v1.x = one_minus_sigmoid(acc[mt][nt][2]);
                v1.y = one_minus_sigmoid(acc[mt][nt][3]);
            }
            *(float2*)(Cg + (size_t)r0 * ldc + c0)       = v0;
            *(float2*)(Cg + (size_t)(r0 + 8) * ldc + c0) = v1;
        }
    }
#undef LDGC
#undef STSC
}

__global__ __launch_bounds__(256) void k_proj_fp16(const float* __restrict__ z0,
                                                   const float* __restrict__ z1,
                                                   const float* __restrict__ z2,
                                                   const float* __restrict__ W,
                                                   const float* __restrict__ b) {
    const float* zs = (blockIdx.z == 0) ? z0 : ((blockIdx.z == 1) ? z1 : z2);
    gemm_fp16(zs, W, g_P[blockIdx.z], b, HD, HF, HD / 16, 0);
}

__global__ __launch_bounds__(256) void k_pair_fp16() {
    const int p = blockIdx.z;
    const int pa = (p == 2) ? 1 : 0;       // pairs: (0,1) (0,2) (1,2)
    const int pb = (p == 0) ? 1 : 2;
    gemm_fp16(g_P[pa], g_P[pb], g_A[p], nullptr, HF, BD, HF / 16, 1);
}

// ============================================================================
// Row L2 normalize of projections: p /= max(||p||, 1e-12)
// ============================================================================
__global__ __launch_bounds__(128) void k_norm() {
    __shared__ float sred[4];
    const int p = blockIdx.y, r = blockIdx.x, tid = threadIdx.x;
    float4* Pr = (float4*)(g_P[p] + (size_t)r * HF);
    float4 v = Pr[tid];
    float s = v.x * v.x + v.y * v.y + v.z * v.z + v.w * v.w;
#pragma unroll
    for (int t = 16; t; t >>= 1) s += __shfl_xor_sync(0xffffffffu, s, t);
    if ((tid & 31) == 0) sred[tid >> 5] = s;
    __syncthreads();
    float tot = sred[0] + sred[1] + sred[2] + sred[3];
    float scl = 1.0f / fmaxf(sqrtf(tot), 1e-12f);
    v.x *= scl; v.y *= scl; v.z *= scl; v.w *= scl;
    Pr[tid] = v;
}

// ============================================================================
// d[i] = (max(sum_j A[i,j], 1e-8))^{-1/2}       (fp32 A, R9-proven)
// ============================================================================
__global__ __launch_bounds__(256) void k_degree() {
    __shared__ float sred[8];
    const int p = blockIdx.y, r = blockIdx.x, tid = threadIdx.x;
    const float4* Ar = (const float4*)(g_A[p] + (size_t)r * BD);
    float s = 0.f;
#pragma unroll
    for (int q = 0; q < 4; q++) {
        float4 v = Ar[tid + q * 256];
        s += (v.x + v.y) + (v.z + v.w);
    }
#pragma unroll
    for (int t = 16; t; t >>= 1) s += __shfl_xor_sync(0xffffffffu, s, t);
    if ((tid & 31) == 0) sred[tid >> 5] = s;
    __syncthreads();
    if (tid == 0) {
        float tot = 0.f;
        for (int w = 0; w < 8; w++) tot += sred[w];
        g_d[p][r] = 1.0f / sqrtf(fmaxf(tot, 1e-8f));
    }
}

// ============================================================================
// JAX threefry2x32 PRNG — partitionable scheme (modern JAX default):
// per-element 64-bit linear-index counter (0, e); 32-bit output = o0 ^ o1.
// ============================================================================
#define TF_R(r) { x0 += x1; x1 = (x1 << (r)) | (x1 >> (32 - (r))); x1 ^= x0; }
__device__ __forceinline__ void tf_hash(unsigned k0, unsigned k1,
                                        unsigned c0, unsigned c1,
                                        unsigned& o0, unsigned& o1) {
    unsigned ks2 = k0 ^ k1 ^ 0x1BD11BDAu;
    unsigned x0 = c0 + k0, x1 = c1 + k1;
    TF_R(13) TF_R(15) TF_R(26) TF_R(6)   x0 += k1;  x1 += ks2 + 1u;
    TF_R(17) TF_R(29) TF_R(16) TF_R(24)  x0 += ks2; x1 += k0  + 2u;
    TF_R(13) TF_R(15) TF_R(26) TF_R(6)   x0 += k0;  x1 += k1  + 3u;
    TF_R(17) TF_R(29) TF_R(16) TF_R(24)  x0 += k1;  x1 += ks2 + 4u;
    TF_R(13) TF_R(15) TF_R(26) TF_R(6)   x0 += ks2; x1 += k0  + 5u;
    o0 = x0; o1 = x1;
}

__device__ __forceinline__ float bits_to_normal(unsigned bits) {
    float f = __uint_as_float((bits >> 9) | 0x3f800000u) - 1.0f;
    const float lo = -0.99999994f;        // nextafter(-1, 0) in fp32
    float u = f * 2.0f + lo;
    u = fmaxf(lo, u);
    return 1.41421356f * erfinvf(u);
}

__global__ __launch_bounds__(256) void k_init() {
    int gid = blockIdx.x * 256 + threadIdx.x;
    if (gid >= 3 * 32768) return;
    int p = gid >> 15;
    int e = gid & 32767;
    unsigned kp0, kp1, o0, o1;
    tf_hash(0u, 42u, 0u, (unsigned)p, kp0, kp1);   // fold_in(key(42), p)
    tf_hash(kp0, kp1, 0u, (unsigned)e, o0, o1);    // counter = (0, e)
    g_V[p][e] = bits_to_normal(o0 ^ o1);
}

// ============================================================================
// Householder QR of 4096x8 panel, SMEM-RESIDENT (column-major, 128 KB dynamic
// smem). LAPACK sgeqr2 + sorg2r conventions; one CTA per pair.
// which==0: factor g_V;  which==1: factor g_LV.
// ============================================================================
#define SH(k, i) sh[(k) * BD + (i)]

__global__ __launch_bounds__(1024) void k_qr(int which) {
    extern __shared__ float sh[];          // [NC][BD] column-major panel
    const int p = blockIdx.x;
    float* __restrict__ Aw = which ? g_LV[p] : g_V[p];
    const int m = BD;
    const int tid = threadIdx.x;
    const int lane = tid & 31;
    const int wid  = tid >> 5;
    __shared__ float tau[NC];
    __shared__ float red[32][NC];
    __shared__ float sred[32];
    __shared__ float sc[2];                // [0]=1/(alpha-beta), [1]=beta

    for (int i = tid; i < m * NC; i += 1024)
        SH(i & 7, i >> 3) = Aw[i];
    __syncthreads();

    // ---------------- factorization (geqr2) ----------------
    for (int j = 0; j < NC; j++) {
        float s = 0.f;
        for (int i = j + 1 + tid; i < m; i += 1024) {
            float v = SH(j, i);
            s += v * v;
        }
#pragma unroll
        for (int t = 16; t; t >>= 1) s += __shfl_xor_sync(0xffffffffu, s, t);
        __syncthreads();
        if (lane == 0) sred[wid] = s;
        __syncthreads();
        if (tid == 0) {
            float ss = 0.f;
            for (int w = 0; w < 32; w++) ss += sred[w];
            float alpha = SH(j, j);
            float t_, scal, beta;
            if (ss == 0.f) { beta = alpha; t_ = 0.f; scal = 0.f; }
            else {
                float nrm = sqrtf(alpha * alpha + ss);
                beta = (alpha >= 0.f) ? -nrm : nrm;   // LAPACK sign convention
                t_   = (beta - alpha) / beta;
                scal = 1.0f / (alpha - beta);
            }
            tau[j] = t_;
            sc[0] = scal; sc[1] = beta;
        }
        __syncthreads();
        const float scal = sc[0];
        const float tj   = tau[j];
        float w[NC];
#pragma unroll
        for (int k = 0; k < NC; k++) w[k] = 0.f;
        for (int i = j + tid; i < m; i += 1024) {
            float v;
            if (i == j) v = 1.f;
            else { v = SH(j, i) * scal; SH(j, i) = v; }
#pragma unroll
            for (int k = 0; k < NC; k++)
                if (k > j) w[k] += v * SH(k, i);
        }
#pragma unroll
        for (int k = 0; k < NC; k++)
#pragma unroll
            for (int t = 16; t; t >>= 1) w[k] += __shfl_xor_sync(0xffffffffu, w[k], t);
        if (lane == 0) {
#pragma unroll
            for (int k = 0; k < NC; k++) red[wid][k] = w[k];
        }
        __syncthreads();
#pragma unroll
        for (int k = 0; k < NC; k++) {
            float t2 = 0.f;
            for (int ww = 0; ww < 32; ww++) t2 += red[ww][k];
            w[k] = t2;
        }
        for (int i = j + tid; i < m; i += 1024) {
            float v = (i == j) ? 1.f : SH(j, i);
#pragma unroll
            for (int k = 0; k < NC; k++)
                if (k > j) SH(k, i) -= tj * w[k] * v;
        }
        if (tid == 0) SH(j, j) = sc[1];
        __syncthreads();
    }

    // ---------------- form Q (sorg2r) ----------------
    for (int j = NC - 1; j >= 0; j--) {
        const float tj = tau[j];
        if (j < NC - 1) {
            float w[NC];
#pragma unroll
            for (int k = 0; k < NC; k++) w[k] = 0.f;
            for (int i = j + tid; i < m; i += 1024) {
                float v = (i == j) ? 1.f : SH(j, i);
#pragma unroll
                for (int k = 0; k < NC; k++)
                    if (k > j) w[k] += v * SH(k, i);
            }
#pragma unroll
            for (int k = 0; k < NC; k++)
#pragma unroll
                for (int t = 16; t; t >>= 1) w[k] += __shfl_xor_sync(0xffffffffu, w[k], t);
            if (lane == 0) {
#pragma unroll
                for (int k = 0; k < NC; k++) red[wid][k] = w[k];
            }
            __syncthreads();
#pragma unroll
            for (int k = 0; k < NC; k++) {
                float t2 = 0.f;
                for (int ww = 0; ww < 32; ww++) t2 += red[ww][k];
                w[k] = t2;
            }
            for (int i = j + tid; i < m; i += 1024) {
                float v = (i == j) ? 1.f : SH(j, i);
#pragma unroll
                for (int k = 0; k < NC; k++)
                    if (k > j) SH(k, i) -= tj * w[k] * v;
            }
            __syncthreads();
        }
        for (int i = tid; i < m; i += 1024) {
            float val;
            if (i < j)       val = 0.f;
            else if (i == j) val = 1.f - tj;
            else             val = -tj * SH(j, i);
            SH(j, i) = val;
        }
        __syncthreads();
    }

    const float* __restrict__ dv = g_d[p];
    for (int i = tid; i < m * NC; i += 1024) {
        float q = SH(i & 7, i >> 3);
        g_V[p][i] = q;
        g_X[p][i] = dv[i >> 3] * q;
    }
}

// ============================================================================
// LV[i,:] = V[i,:] - d[i] * (A[i,:] @ X)      (fp32 A, R9-proven layout)
// ============================================================================
__global__ __launch_bounds__(256) void k_matvec() {
    const int p = blockIdx.y;
    const int warp = threadIdx.x >> 5, lane = threadIdx.x & 31;
    const int row = blockIdx.x * 8 + warp;
    __shared__ float sX[512 * NC];
    const float* __restrict__ Ar = g_A[p] + (size_t)row * BD;
    const float* __restrict__ Xg = g_X[p];
    float acc[8] = {0, 0, 0, 0, 0, 0, 0, 0};
    for (int t0 = 0; t0 < BD; t0 += 512) {
        __syncthreads();
        for (int i = threadIdx.x; i < 512 * NC / 4; i += 256)
            ((float4*)sX)[i] = ((const float4*)(Xg + t0 * NC))[i];
        __syncthreads();
        for (int t = lane; t < 512; t += 32) {
            float a = Ar[t0 + t];
            float4 x0 = *(const float4*)(sX + t * NC);
            float4 x1 = *(const float4*)(sX + t * NC + 4);
            acc[0] += a * x0.x; acc[1] += a * x0.y;
            acc[2] += a * x0.z; acc[3] += a * x0.w;
            acc[4] += a * x1.x; acc[5] += a * x1.y;
            acc[6] += a * x1.z; acc[7] += a * x1.w;
        }
    }
#pragma unroll
    for (int k = 0; k < 8; k++)
#pragma unroll
        for (int t = 16; t; t >>= 1) acc[k] += __shfl_xor_sync(0xffffffffu, acc[k], t);
    if (lane == 0) {
        float di = g_d[p][row];
#pragma unroll
        for (int k = 0; k < 8; k++)
            g_LV[p][row * NC + k] = g_V[p][row * NC + k] - di * acc[k];
    }
}

// ============================================================================
// out = LayerNorm(GELU(spec @ W_out^T + b_out)) ; spec = concat(V0,V1,V2)
// ============================================================================
__global__ __launch_bounds__(128) void k_final(const float* __restrict__ Wo,
                                               const float* __restrict__ bo,
                                               const float* __restrict__ lg,
                                               const float* __restrict__ lb,
                                               float* __restrict__ out) {
    const int r = blockIdx.x, tid = threadIdx.x;
    __shared__ float spec[24];
    __shared__ float sred[4];
    if (tid < 24) spec[tid] = g_V[tid >> 3][r * NC + (tid & 7)];
    __syncthreads();
    float x[4];
    float s = 0.f;
#pragma unroll
    for (int q = 0; q < 4; q++) {
        int j = tid + q * 128;
        const float* wr = Wo + j * 24;
        float acc = bo[j];
#pragma unroll
        for (int c = 0; c < 24; c++) acc += spec[c] * wr[c];
        float gl = 0.5f * acc * (1.0f + erff(acc * 0.70710678118654752f));
        x[q] = gl; s += gl;
    }
#pragma unroll
    for (int t = 16; t; t >>= 1) s += __shfl_xor_sync(0xffffffffu, s, t);
    if ((tid & 31) == 0) sred[tid >> 5] = s;
    __syncthreads();
    float mu = (sred[0] + sred[1] + sred[2] + sred[3]) * (1.0f / HF);
    float s2 = 0.f;
#pragma unroll
    for (int q = 0; q < 4; q++) {
        float d = x[q] - mu;
        s2 += d * d;
    }
#pragma unroll
    for (int t = 16; t; t >>= 1) s2 += __shfl_xor_sync(0xffffffffu, s2, t);
    __syncthreads();
    if ((tid & 31) == 0) sred[tid >> 5] = s2;
    __syncthreads();
    float var = (sred[0] + sred[1] + sred[2] + sred[3]) * (1.0f / HF);
    float inv = 1.0f / sqrtf(var + 1e-5f);
#pragma unroll
    for (int q = 0; q < 4; q++) {
        int j = tid + q * 128;
        out[(size_t)r * HF + j] = (x[q] - mu) * inv * lg[j] + lb[j];
    }
}

// ============================================================================
// Launch sequence (graph-capturable)
// ============================================================================
extern "C" void kernel_launch(void* const* d_in, const int* in_sizes, int n_in,
                              void* d_out, int out_size) {
    const float* zt = (const float*)d_in[0];
    const float* za = (const float*)d_in[1];
    const float* zf = (const float*)d_in[2];
    const float* Wp = (const float*)d_in[3];
    const float* bp = (const float*)d_in[4];
    const float* Wo = (const float*)d_in[5];
    const float* bo = (const float*)d_in[6];
    const float* lg = (const float*)d_in[7];
    const float* lb = (const float*)d_in[8];
    float* out = (float*)d_out;

    const int QR_SMEM = BD * NC * sizeof(float);   // 128 KB dynamic smem
    cudaFuncSetAttribute(k_qr, cudaFuncAttributeMaxDynamicSharedMemorySize, QR_SMEM);

    k_proj_fp16<<<dim3(HF / 128, BD / 128, 3), 256>>>(zt, za, zf, Wp, bp);
    k_norm<<<dim3(BD, 3), 128>>>();
    k_pair_fp16<<<dim3(BD / 128, BD / 128, 3), 256>>>();
    k_degree<<<dim3(BD, 3), 256>>>();
    k_init<<<(3 * 32768 + 255) / 256, 256>>>();
    k_qr<<<3, 1024, QR_SMEM>>>(0);
    for (int it = 0; it < 5; it++) {
        k_matvec<<<dim3(BD / 8, 3), 256>>>();
        k_qr<<<3, 1024, QR_SMEM>>>(1);
    }
    k_final<<<BD, 128>>>(Wo, bo, lg, lb, out);
}